// round 5
// baseline (speedup 1.0000x reference)
#include <cuda_runtime.h>
#include <cuda_bf16.h>

#define BATCH      524288
#define N_QUBITS   16
#define NUM_CLS    10
#define TPB        256            // 8 warps
#define TILES      4              // tiles (of TPB rows) per block, pipelined
#define ROWS_PER_BLOCK (TPB * TILES)   // 1024
#define NWARPS     (TPB / 32)

// Output[b, s] = tail_s / sum_{s'<10} tail_s' where tail depends only on
// qubits 12..15 (states 0..9 have zero bits for qubits 0..11; the common
// prod_{i<12} p0_i factor cancels in the normalization).
// Half-angle identity: cos^2(t/2) = (1+cos t)/2, sin^2(t/2) = (1-cos t)/2.
//
// Pipelined streaming: each block walks TILES tiles; the LDG for tile t+1 is
// issued before compute/store of tile t, so in steady state every warp has a
// read in flight while it writes -> DRAM sees mixed, continuous traffic
// instead of a read burst / idle / write burst.
__global__ __launch_bounds__(TPB, 6) void qllp_kernel(
    const float* __restrict__ x,       // [BATCH, 16]
    const float* __restrict__ params,  // [16]
    float*       __restrict__ out)     // [BATCH, 10]
{
    // Double-buffered per-warp staging: 2 * 8 warps * 32 rows * 10 floats = 20 KB.
    __shared__ float s_out[2][NWARPS][32 * NUM_CLS];

    const int lane = threadIdx.x & 31;
    const int warp = threadIdx.x >> 5;
    const size_t blockRow0 = (size_t)blockIdx.x * ROWS_PER_BLOCK;
    const int wrow = warp * 32 + lane;          // row offset within a tile

    const float pr12 = __ldg(&params[12]);
    const float pr13 = __ldg(&params[13]);
    const float pr14 = __ldg(&params[14]);
    const float pr15 = __ldg(&params[15]);

    const float PI = 3.14159265358979323846f;

    // Prologue: prefetch tile 0.
    float4 v = *reinterpret_cast<const float4*>(
        x + (blockRow0 + wrow) * N_QUBITS + 12);

    #pragma unroll
    for (int t = 0; t < TILES; t++) {
        // Prefetch next tile while this one computes/stores.
        float4 vn;
        if (t + 1 < TILES)
            vn = *reinterpret_cast<const float4*>(
                x + (blockRow0 + (size_t)(t + 1) * TPB + wrow) * N_QUBITS + 12);

        const float c0 = __cosf(PI * v.x + pr12);   // qubit 12
        const float c1 = __cosf(PI * v.y + pr13);   // qubit 13
        const float c2 = __cosf(PI * v.z + pr14);   // qubit 14
        const float c3 = __cosf(PI * v.w + pr15);   // qubit 15

        const float a0 = 0.5f + 0.5f * c0, b0 = 0.5f - 0.5f * c0;
        const float a1 = 0.5f + 0.5f * c1, b1 = 0.5f - 0.5f * c1;
        const float a2 = 0.5f + 0.5f * c2, b2 = 0.5f - 0.5f * c2;
        const float a3 = 0.5f + 0.5f * c3, b3 = 0.5f - 0.5f * c3;

        // bits[s,i] = (s >> (15-i)) & 1 -> qubit12 = bit3 ... qubit15 = bit0
        const float m00 = a1 * a2, m01 = a1 * b2, m10 = b1 * a2, m11 = b1 * b2;
        const float g0 = m00 * a3, g1 = m00 * b3, g2 = m01 * a3, g3 = m01 * b3;
        const float g4 = m10 * a3, g5 = m10 * b3, g6 = m11 * a3, g7 = m11 * b3;

        float tv[NUM_CLS];
        tv[0] = a0 * g0;  tv[1] = a0 * g1;  tv[2] = a0 * g2;  tv[3] = a0 * g3;
        tv[4] = a0 * g4;  tv[5] = a0 * g5;  tv[6] = a0 * g6;  tv[7] = a0 * g7;
        tv[8] = b0 * g0;  tv[9] = b0 * g1;

        float sum = tv[0];
        #pragma unroll
        for (int s = 1; s < NUM_CLS; s++) sum += tv[s];
        const float inv = __fdividef(1.0f, sum);

        // Stage as 5 STS.64 per row (8B-aligned: 40B row stride).
        float2* dst2 = reinterpret_cast<float2*>(&s_out[t & 1][warp][lane * NUM_CLS]);
        #pragma unroll
        for (int s = 0; s < NUM_CLS / 2; s++)
            dst2[s] = make_float2(tv[2 * s] * inv, tv[2 * s + 1] * inv);

        __syncwarp();

        // Dense coalesced writeback of this warp's 32 rows: 160 float2, 5/lane.
        float2* o2 = reinterpret_cast<float2*>(
            out + (blockRow0 + (size_t)t * TPB + (size_t)warp * 32) * NUM_CLS);
        const float2* s2 = reinterpret_cast<const float2*>(s_out[t & 1][warp]);
        #pragma unroll
        for (int i = 0; i < (32 * NUM_CLS) / (2 * 32); i++)   // 5 iters
            o2[i * 32 + lane] = s2[i * 32 + lane];

        v = vn;
        // Double buffering (t&1) makes it safe to STS the next tile without
        // waiting for this tile's LDS to drain.
    }
}

extern "C" void kernel_launch(void* const* d_in, const int* in_sizes, int n_in,
                              void* d_out, int out_size) {
    const float* x      = (const float*)d_in[0];
    const float* params = (const float*)d_in[1];
    float*       out    = (float*)d_out;
    qllp_kernel<<<BATCH / ROWS_PER_BLOCK, TPB>>>(x, params, out);
}